// round 10
// baseline (speedup 1.0000x reference)
#include <cuda_runtime.h>
#include <cstdint>

// ---------------------------------------------------------------------------
// InstanceModelClassic: rigid-transform trilinear resampling of a 256^3 volume
// Smem-tiled gather, conflict-free pitches, single branch-free sample path.
// ---------------------------------------------------------------------------

__device__ float g_T[12];   // 3x4 rows of composed voxel->voxel transform

__device__ static void mat4_inv(const float* A, float* Ainv) {
    float M[4][8];
    for (int r = 0; r < 4; r++) {
        for (int c = 0; c < 4; c++) {
            M[r][c] = A[r * 4 + c];
            M[r][4 + c] = (r == c) ? 1.0f : 0.0f;
        }
    }
    for (int col = 0; col < 4; col++) {
        int piv = col;
        float best = fabsf(M[col][col]);
        for (int r = col + 1; r < 4; r++) {
            float v = fabsf(M[r][col]);
            if (v > best) { best = v; piv = r; }
        }
        if (piv != col)
            for (int c = 0; c < 8; c++) {
                float t = M[col][c]; M[col][c] = M[piv][c]; M[piv][c] = t;
            }
        float inv_p = 1.0f / M[col][col];
        for (int c = 0; c < 8; c++) M[col][c] *= inv_p;
        for (int r = 0; r < 4; r++) {
            if (r == col) continue;
            float f = M[r][col];
            if (f != 0.0f)
                for (int c = 0; c < 8; c++) M[r][c] -= f * M[col][c];
        }
    }
    for (int r = 0; r < 4; r++)
        for (int c = 0; c < 4; c++)
            Ainv[r * 4 + c] = M[r][4 + c];
}

__device__ static void mm4(const float* A, const float* B, float* C) {
    for (int r = 0; r < 4; r++)
        for (int c = 0; c < 4; c++) {
            float s = 0.0f;
            for (int k = 0; k < 4; k++) s += A[r * 4 + k] * B[k * 4 + c];
            C[r * 4 + c] = s;
        }
}

__global__ void setup_transform_kernel(const float* __restrict__ rotation,
                                       const float* __restrict__ translation,
                                       const float* __restrict__ ref_v2r,
                                       const float* __restrict__ flo_v2r) {
    float cx = cosf(rotation[0]), cy = cosf(rotation[1]), cz = cosf(rotation[2]);
    float sx = sinf(rotation[0]), sy = sinf(rotation[1]), sz = sinf(rotation[2]);

    float Rx[9] = {1, 0, 0,   0, cx, -sx,   0, sx, cx};
    float Ry[9] = {cy, 0, sy, 0, 1, 0,      -sy, 0, cy};
    float Rz[9] = {cz, -sz, 0, sz, cz, 0,   0, 0, 1};
    float Ryz[9], R[9];
    for (int r = 0; r < 3; r++)
        for (int c = 0; c < 3; c++) {
            float s = 0.0f;
            for (int k = 0; k < 3; k++) s += Ry[r * 3 + k] * Rz[k * 3 + c];
            Ryz[r * 3 + c] = s;
        }
    for (int r = 0; r < 3; r++)
        for (int c = 0; c < 3; c++) {
            float s = 0.0f;
            for (int k = 0; k < 3; k++) s += Rx[r * 3 + k] * Ryz[k * 3 + c];
            R[r * 3 + c] = s;
        }

    float Trig[16];
    for (int r = 0; r < 3; r++) {
        for (int c = 0; c < 3; c++) Trig[r * 4 + c] = R[r * 3 + c];
        Trig[r * 4 + 3] = translation[r];
    }
    Trig[12] = 0.0f; Trig[13] = 0.0f; Trig[14] = 0.0f; Trig[15] = 1.0f;

    float Finv[16], tmp[16], T[16];
    mat4_inv(flo_v2r, Finv);
    mm4(Trig, ref_v2r, tmp);
    mm4(Finv, tmp, T);

    for (int i = 0; i < 12; i++) g_T[i] = T[i];
}

// ----------------------------------------------------------------------------
// Tile geometry.
//   Output tile: TI x TJ x TK = 8 x 16 x 32  (4096 voxels, 4096 blocks)
//   Staged region: SMX x SMY rows, FULL pitch 64 floats staged per row.
//   OY = 64  (== 0 mod 32 banks), OX = 64*21 = 1344 (== 0 mod 32) ->
//   zero bank conflicts on all 8 gather taps.
//   smem = 14*21*64*4 = 75264 B -> 3 CTA/SM, 48 warps/SM.
// ----------------------------------------------------------------------------
constexpr int TI = 8, TJ = 16, TK = 32;
constexpr int SMX = 14, SMY = 21;
constexpr int OY = 64;                    // z pitch (floats)
constexpr int OX = OY * SMY;              // 1344
constexpr int ZCAP = 44;                  // usable z extent for fits-check
constexpr int SM_FLOATS = SMX * SMY * OY; // 18816
constexpr int SM_BYTES = SM_FLOATS * 4;   // 75264
constexpr int NTHREADS = 512;
constexpr int BASE_LIM = SM_FLOATS - (OX + OY + 2);  // 17406

__device__ __forceinline__ float axis_min(float t, int lo, int len) {
    return (t >= 0.0f) ? t * (float)lo : t * (float)(lo + len - 1);
}
__device__ __forceinline__ float axis_max(float t, int lo, int len) {
    return (t >= 0.0f) ? t * (float)(lo + len - 1) : t * (float)lo;
}

__device__ __forceinline__ void cp_async16(unsigned int smem_dst, const void* gsrc) {
    asm volatile("cp.async.cg.shared.global [%0], [%1], 16;\n"
                 :: "r"(smem_dst), "l"(gsrc) : "memory");
}
__device__ __forceinline__ void cp_async_wait_all() {
    asm volatile("cp.async.commit_group;\ncp.async.wait_group 0;\n" ::: "memory");
}

__global__ void __launch_bounds__(NTHREADS, 3)
tiled_trilinear_kernel(const float* __restrict__ img, float* __restrict__ out) {
    extern __shared__ float tile[];

    const int bid = blockIdx.x;
    const int k0 = (bid & 7) << 5;           // 8 k-tiles of 32
    const int j0 = ((bid >> 3) & 15) << 4;   // 16 j-tiles of 16
    const int i0 = (bid >> 7) << 3;          // 32 i-tiles of 8

    const float T00 = g_T[0], T01 = g_T[1],  T02 = g_T[2],  T03 = g_T[3];
    const float T10 = g_T[4], T11 = g_T[5],  T12 = g_T[6],  T13 = g_T[7];
    const float T20 = g_T[8], T21 = g_T[9],  T22 = g_T[10], T23 = g_T[11];

    // Input-space bbox of this output tile (block-uniform).
    const float mnI = T03 + axis_min(T00, i0, TI) + axis_min(T01, j0, TJ) + axis_min(T02, k0, TK);
    const float mxI = T03 + axis_max(T00, i0, TI) + axis_max(T01, j0, TJ) + axis_max(T02, k0, TK);
    const float mnJ = T13 + axis_min(T10, i0, TI) + axis_min(T11, j0, TJ) + axis_min(T12, k0, TK);
    const float mxJ = T13 + axis_max(T10, i0, TI) + axis_max(T11, j0, TJ) + axis_max(T12, k0, TK);
    const float mnK = T23 + axis_min(T20, i0, TI) + axis_min(T21, j0, TJ) + axis_min(T22, k0, TK);
    const float mxK = T23 + axis_max(T20, i0, TI) + axis_max(T21, j0, TJ) + axis_max(T22, k0, TK);

    const int loX  = max(__float2int_rd(mnI), 0);
    const int loY  = max(__float2int_rd(mnJ), 0);
    const int loZ  = max(__float2int_rd(mnK), 0);
    const int zloA = loZ & ~3;                       // 16B-aligned z origin
    const int hiX  = min(__float2int_rd(mxI) + 1, 255);
    const int hiY  = min(__float2int_rd(mxJ) + 1, 255);
    const int hiZ  = min(__float2int_rd(mxK) + 1, 255);

    const bool fits = (hiX - loX < SMX) && (hiY - loY < SMY) && (hiZ - zloA < ZCAP);

    const int tid = threadIdx.x;
    const int kl = tid & 31;        // k lane (warp-contiguous)
    const int tg = tid >> 5;        // j row within tile
    const int k = k0 + kl;
    const int j = j0 + tg;
    const float fk = (float)k, fj = (float)j;

    // per-thread (j,k)-dependent bases: II = fmaf(T00, fi, IIb)
    const float IIb = fmaf(T01, fj, fmaf(T02, fk, T03));
    const float JJb = fmaf(T11, fj, fmaf(T12, fk, T13));
    const float KKb = fmaf(T21, fj, fmaf(T22, fk, T23));

    float* outp = out + (((i0 << 8) | j) << 8 | k);

    if (fits) {
        // ---- stage FULL 64-float pitch per row; shift-only index decode ----
        // 294 rows x 16 quads = 4704 cp.async of 16B. dst byte offset = idx*16.
        {
            const unsigned int smem_u32 =
                (unsigned int)__cvta_generic_to_shared(&tile[0]);
            constexpr int NQUADS = SMX * SMY * 16;   // 4704
            for (int idx = tid; idx < NQUADS; idx += NTHREADS) {
                const int r  = idx >> 4;             // row (xp*SMY + yp)
                const int q  = idx & 15;             // quad within row
                const int xp = r / SMY;              // one magic-div
                const int yp = r - xp * SMY;
                const int xg = min(loX + xp, 255);
                const int yg = min(loY + yp, 255);
                const int zg = min(zloA + (q << 2), 252);  // in-bounds; extra slots never carry weight
                cp_async16(smem_u32 + (idx << 4),    // 16 bytes per quad
                           img + ((xg << 16) | (yg << 8) | zg));
            }
            cp_async_wait_all();
        }
        __syncthreads();

        // tile-space: base = (x0-loX)*OX + (y0-loY)*OY + (z0-zloA)
        const int Coff = -(loX * OX + loY * OY + zloA);
        const float* tilep = tile;

        // ------------- single branch-free sample path for all voxels -------------
        float fi = (float)i0;
#pragma unroll
        for (int e = 0; e < TI; e++) {
            const float II = fmaf(T00, fi, IIb);
            const float JJ = fmaf(T10, fi, JJb);
            const float KK = fmaf(T20, fi, KKb);
            fi += 1.0f;

            const bool ok = (II > 0.0f) & (JJ > 0.0f) & (KK > 0.0f) &
                            (II <= 255.0f) & (JJ <= 255.0f) & (KK <= 255.0f);

            const float fx = floorf(II);
            const float fy = floorf(JJ);
            const float fz = floorf(KK);
            const float wcx = II - fx, wfx = 1.0f - wcx;
            const float wcy = JJ - fy, wfy = 1.0f - wcy;
            const float wcz = KK - fz, wfz = 1.0f - wcz;

            // exact float linear index (|value| < 2^24), then safety clamp.
            // Taps whose +1 face would leave the staged region carry weight 0
            // (coord exactly on an integer face) or are discarded by ok-select;
            // all reachable smem slots hold finite staged data.
            int base = __float2int_rn(
                fmaf(fx, (float)OX, fmaf(fy, (float)OY, fz))) + Coff;
            base = min(max(base, 0), BASE_LIM);
            const float* p = tilep + base;

            const float v000 = p[0],        v001 = p[1];
            const float v010 = p[OY],       v011 = p[OY + 1];
            const float v100 = p[OX],       v101 = p[OX + 1];
            const float v110 = p[OX + OY],  v111 = p[OX + OY + 1];

            // level-wise weighted sums (all-positive weights, no cancellation)
            const float c00 = fmaf(v001, wcz, v000 * wfz);
            const float c01 = fmaf(v011, wcz, v010 * wfz);
            const float c10 = fmaf(v101, wcz, v100 * wfz);
            const float c11 = fmaf(v111, wcz, v110 * wfz);
            const float c0  = fmaf(c01, wcy, c00 * wfy);
            const float c1  = fmaf(c11, wcy, c10 * wfy);
            float v         = fmaf(c1,  wcx, c0  * wfx);

            v = ok ? v : 0.0f;
            outp[e << 16] = v;
        }
    } else {
        // ---------------- fallback: direct global gather ----------------
        float fi = (float)i0;
        for (int e = 0; e < TI; e++) {
            const float II = fmaf(T00, fi, IIb);
            const float JJ = fmaf(T10, fi, JJb);
            const float KK = fmaf(T20, fi, KKb);
            fi += 1.0f;

            const bool ok = (II > 0.0f) & (JJ > 0.0f) & (KK > 0.0f) &
                            (II <= 255.0f) & (JJ <= 255.0f) & (KK <= 255.0f);
            float v = 0.0f;
            if (ok) {
                const int x0 = __float2int_rd(II);
                const int y0 = __float2int_rd(JJ);
                const int z0 = __float2int_rd(KK);
                const float wcx = II - (float)x0, wfx = 1.0f - wcx;
                const float wcy = JJ - (float)y0, wfy = 1.0f - wcy;
                const float wcz = KK - (float)z0, wfz = 1.0f - wcz;

                const int ox = (x0 < 255) ? 65536 : 0;
                const int oy = (y0 < 255) ? 256 : 0;
                const int oz = (z0 < 255) ? 1 : 0;

                const float* p = img + ((x0 << 16) | (y0 << 8) | z0);
                const float v000 = __ldg(p),            v001 = __ldg(p + oz);
                const float v010 = __ldg(p + oy),       v011 = __ldg(p + oy + oz);
                const float v100 = __ldg(p + ox),       v101 = __ldg(p + ox + oz);
                const float v110 = __ldg(p + ox + oy),  v111 = __ldg(p + ox + oy + oz);

                const float c00 = fmaf(v001, wcz, v000 * wfz);
                const float c01 = fmaf(v011, wcz, v010 * wfz);
                const float c10 = fmaf(v101, wcz, v100 * wfz);
                const float c11 = fmaf(v111, wcz, v110 * wfz);
                const float c0  = fmaf(c01, wcy, c00 * wfy);
                const float c1  = fmaf(c11, wcy, c10 * wfy);
                v               = fmaf(c1,  wcx, c0  * wfx);
            }
            outp[e << 16] = v;
        }
    }
}

extern "C" void kernel_launch(void* const* d_in, const int* in_sizes, int n_in,
                              void* d_out, int out_size) {
    const float* img         = (const float*)d_in[0];
    const float* rotation    = (const float*)d_in[1];
    const float* translation = (const float*)d_in[2];
    const float* ref_v2r     = (const float*)d_in[3];
    const float* flo_v2r     = (const float*)d_in[4];
    float* out = (float*)d_out;

    setup_transform_kernel<<<1, 1>>>(rotation, translation, ref_v2r, flo_v2r);

    static bool attr_set = false;
    if (!attr_set) {
        cudaFuncSetAttribute(tiled_trilinear_kernel,
                             cudaFuncAttributeMaxDynamicSharedMemorySize, SM_BYTES);
        attr_set = true;
    }

    tiled_trilinear_kernel<<<4096, NTHREADS, SM_BYTES>>>(img, out);
}

// round 11
// speedup vs baseline: 1.2764x; 1.2764x over previous
#include <cuda_runtime.h>
#include <cuda.h>
#include <cstdint>

// ---------------------------------------------------------------------------
// InstanceModelClassic: rigid-transform trilinear resampling of a 256^3 volume
// TMA-staged smem tile (conflict-free 64-float pitch), interior fast path.
// ---------------------------------------------------------------------------

__device__ float g_T[12];   // 3x4 rows of composed voxel->voxel transform

__device__ static void mat4_inv(const float* A, float* Ainv) {
    float M[4][8];
    for (int r = 0; r < 4; r++) {
        for (int c = 0; c < 4; c++) {
            M[r][c] = A[r * 4 + c];
            M[r][4 + c] = (r == c) ? 1.0f : 0.0f;
        }
    }
    for (int col = 0; col < 4; col++) {
        int piv = col;
        float best = fabsf(M[col][col]);
        for (int r = col + 1; r < 4; r++) {
            float v = fabsf(M[r][col]);
            if (v > best) { best = v; piv = r; }
        }
        if (piv != col)
            for (int c = 0; c < 8; c++) {
                float t = M[col][c]; M[col][c] = M[piv][c]; M[piv][c] = t;
            }
        float inv_p = 1.0f / M[col][col];
        for (int c = 0; c < 8; c++) M[col][c] *= inv_p;
        for (int r = 0; r < 4; r++) {
            if (r == col) continue;
            float f = M[r][col];
            if (f != 0.0f)
                for (int c = 0; c < 8; c++) M[r][c] -= f * M[col][c];
        }
    }
    for (int r = 0; r < 4; r++)
        for (int c = 0; c < 4; c++)
            Ainv[r * 4 + c] = M[r][4 + c];
}

__device__ static void mm4(const float* A, const float* B, float* C) {
    for (int r = 0; r < 4; r++)
        for (int c = 0; c < 4; c++) {
            float s = 0.0f;
            for (int k = 0; k < 4; k++) s += A[r * 4 + k] * B[k * 4 + c];
            C[r * 4 + c] = s;
        }
}

__global__ void setup_transform_kernel(const float* __restrict__ rotation,
                                       const float* __restrict__ translation,
                                       const float* __restrict__ ref_v2r,
                                       const float* __restrict__ flo_v2r) {
    float cx = cosf(rotation[0]), cy = cosf(rotation[1]), cz = cosf(rotation[2]);
    float sx = sinf(rotation[0]), sy = sinf(rotation[1]), sz = sinf(rotation[2]);

    float Rx[9] = {1, 0, 0,   0, cx, -sx,   0, sx, cx};
    float Ry[9] = {cy, 0, sy, 0, 1, 0,      -sy, 0, cy};
    float Rz[9] = {cz, -sz, 0, sz, cz, 0,   0, 0, 1};
    float Ryz[9], R[9];
    for (int r = 0; r < 3; r++)
        for (int c = 0; c < 3; c++) {
            float s = 0.0f;
            for (int k = 0; k < 3; k++) s += Ry[r * 3 + k] * Rz[k * 3 + c];
            Ryz[r * 3 + c] = s;
        }
    for (int r = 0; r < 3; r++)
        for (int c = 0; c < 3; c++) {
            float s = 0.0f;
            for (int k = 0; k < 3; k++) s += Rx[r * 3 + k] * Ryz[k * 3 + c];
            R[r * 3 + c] = s;
        }

    float Trig[16];
    for (int r = 0; r < 3; r++) {
        for (int c = 0; c < 3; c++) Trig[r * 4 + c] = R[r * 3 + c];
        Trig[r * 4 + 3] = translation[r];
    }
    Trig[12] = 0.0f; Trig[13] = 0.0f; Trig[14] = 0.0f; Trig[15] = 1.0f;

    float Finv[16], tmp[16], T[16];
    mat4_inv(flo_v2r, Finv);
    mm4(Trig, ref_v2r, tmp);
    mm4(Finv, tmp, T);

    for (int i = 0; i < 12; i++) g_T[i] = T[i];
}

// ----------------------------------------------------------------------------
// Tile geometry.
//   Output tile: TI x TJ x TK = 8 x 16 x 32  (4096 voxels, 4096 blocks)
//   Staged via TMA box (z,y,x) = (64, 21, 14) fp32, OOB zero-filled.
//   OY = 64 floats (256B == 0 mod 32 banks), OX = 64*21 = 1344 (== 0 mod 32)
//   -> zero bank conflicts on all 8 gather taps.
//   smem = 75264 B tile + mbarrier -> 3 CTA/SM, 48 warps/SM.
// ----------------------------------------------------------------------------
constexpr int TI = 8, TJ = 16, TK = 32;
constexpr int SMX = 14, SMY = 21;
constexpr int OY = 64;                    // z pitch (floats)
constexpr int OX = OY * SMY;              // 1344
constexpr int SM_FLOATS = SMX * SMY * OY; // 18816
constexpr int TILE_BYTES = SM_FLOATS * 4; // 75264
constexpr int SM_BYTES = TILE_BYTES + 16; // + mbarrier slot
constexpr int NTHREADS = 512;
constexpr int BASE_LIM = SM_FLOATS - (OX + OY + 2);  // 17406

__device__ __forceinline__ float axis_min(float t, int lo, int len) {
    return (t >= 0.0f) ? t * (float)lo : t * (float)(lo + len - 1);
}
__device__ __forceinline__ float axis_max(float t, int lo, int len) {
    return (t >= 0.0f) ? t * (float)(lo + len - 1) : t * (float)lo;
}

__device__ __forceinline__ unsigned int smem_u32(const void* p) {
    return (unsigned int)__cvta_generic_to_shared(p);
}

__device__ __forceinline__ void mbar_init(unsigned int mbar, unsigned int cnt) {
    asm volatile("mbarrier.init.shared.b64 [%0], %1;" :: "r"(mbar), "r"(cnt) : "memory");
}
__device__ __forceinline__ void mbar_expect_tx(unsigned int mbar, unsigned int bytes) {
    asm volatile("mbarrier.arrive.expect_tx.shared.b64 _, [%0], %1;"
                 :: "r"(mbar), "r"(bytes) : "memory");
}
__device__ __forceinline__ void mbar_wait_parity0(unsigned int mbar) {
    asm volatile(
        "{\n\t"
        ".reg .pred P1;\n\t"
        "WAIT_LOOP_%=:\n\t"
        "mbarrier.try_wait.parity.acquire.cta.shared::cta.b64 P1, [%0], 0, 0x989680;\n\t"
        "@P1 bra.uni WAIT_DONE_%=;\n\t"
        "bra.uni WAIT_LOOP_%=;\n\t"
        "WAIT_DONE_%=:\n\t"
        "}"
        :: "r"(mbar) : "memory");
}
__device__ __forceinline__ void tma_load_3d(unsigned int dst, const CUtensorMap* tmap,
                                            int c0, int c1, int c2, unsigned int mbar) {
    asm volatile(
        "cp.async.bulk.tensor.3d.shared::cta.global.tile.mbarrier::complete_tx::bytes "
        "[%0], [%1, {%2, %3, %4}], [%5];"
        :: "r"(dst), "l"(tmap), "r"(c0), "r"(c1), "r"(c2), "r"(mbar) : "memory");
}

// ---------------------------- TMA-staged kernel -----------------------------
__global__ void __launch_bounds__(NTHREADS, 3)
tma_trilinear_kernel(const __grid_constant__ CUtensorMap tmap,
                     const float* __restrict__ img, float* __restrict__ out) {
    extern __shared__ __align__(128) float tile[];

    const int bid = blockIdx.x;
    const int k0 = (bid & 7) << 5;           // 8 k-tiles of 32
    const int j0 = ((bid >> 3) & 15) << 4;   // 16 j-tiles of 16
    const int i0 = (bid >> 7) << 3;          // 32 i-tiles of 8

    const float T00 = g_T[0], T01 = g_T[1],  T02 = g_T[2],  T03 = g_T[3];
    const float T10 = g_T[4], T11 = g_T[5],  T12 = g_T[6],  T13 = g_T[7];
    const float T20 = g_T[8], T21 = g_T[9],  T22 = g_T[10], T23 = g_T[11];

    // Input-space bbox of this output tile (block-uniform).
    const float mnI = T03 + axis_min(T00, i0, TI) + axis_min(T01, j0, TJ) + axis_min(T02, k0, TK);
    const float mxI = T03 + axis_max(T00, i0, TI) + axis_max(T01, j0, TJ) + axis_max(T02, k0, TK);
    const float mnJ = T13 + axis_min(T10, i0, TI) + axis_min(T11, j0, TJ) + axis_min(T12, k0, TK);
    const float mxJ = T13 + axis_max(T10, i0, TI) + axis_max(T11, j0, TJ) + axis_max(T12, k0, TK);
    const float mnK = T23 + axis_min(T20, i0, TI) + axis_min(T21, j0, TJ) + axis_min(T22, k0, TK);
    const float mxK = T23 + axis_max(T20, i0, TI) + axis_max(T21, j0, TJ) + axis_max(T22, k0, TK);

    const int loX  = max(__float2int_rd(mnI), 0);
    const int loY  = max(__float2int_rd(mnJ), 0);
    const int loZ  = max(__float2int_rd(mnK), 0);
    const int zloA = loZ & ~3;               // 16B-aligned z origin
    const int hiX  = min(__float2int_rd(mxI) + 1, 255);
    const int hiY  = min(__float2int_rd(mxJ) + 1, 255);
    const int hiZ  = min(__float2int_rd(mxK) + 1, 255);

    const bool fits = (hiX - loX < SMX) && (hiY - loY < SMY) && (hiZ - zloA < OY);

    const int tid = threadIdx.x;
    const int kl = tid & 31;        // k lane (warp-contiguous)
    const int tg = tid >> 5;        // j row within tile
    const int k = k0 + kl;
    const int j = j0 + tg;
    const float fk = (float)k, fj = (float)j;

    const float IIb = fmaf(T01, fj, fmaf(T02, fk, T03));
    const float JJb = fmaf(T11, fj, fmaf(T12, fk, T13));
    const float KKb = fmaf(T21, fj, fmaf(T22, fk, T23));

    float* outp = out + (((i0 << 8) | j) << 8 | k);

    if (fits) {
        // ---- one TMA bulk load stages the whole tile; OOB zero-filled ----
        const unsigned int mbar = smem_u32(&tile[SM_FLOATS]);
        if (tid == 0) {
            mbar_init(mbar, 1);
        }
        __syncthreads();
        if (tid == 0) {
            mbar_expect_tx(mbar, TILE_BYTES);
            tma_load_3d(smem_u32(&tile[0]), &tmap, zloA, loY, loX, mbar);
        }
        mbar_wait_parity0(mbar);

        const int Coff = -(loX * OX + loY * OY + zloA);
        const float* tilep = tile;

        const bool interior = (mnI > 0.01f) && (mxI < 254.99f) &&
                              (mnJ > 0.01f) && (mxJ < 254.99f) &&
                              (mnK > 0.01f) && (mxK < 254.99f);

        if (interior) {
            float fi = (float)i0;
#pragma unroll
            for (int e = 0; e < TI; e++) {
                const float II = fmaf(T00, fi, IIb);
                const float JJ = fmaf(T10, fi, JJb);
                const float KK = fmaf(T20, fi, KKb);
                fi += 1.0f;

                const float fx = floorf(II);
                const float fy = floorf(JJ);
                const float fz = floorf(KK);
                const float wcx = II - fx, wfx = 1.0f - wcx;
                const float wcy = JJ - fy, wfy = 1.0f - wcy;
                const float wcz = KK - fz, wfz = 1.0f - wcz;

                const int base = __float2int_rn(
                    fmaf(fx, (float)OX, fmaf(fy, (float)OY, fz))) + Coff;
                const float* p = tilep + base;

                const float v000 = p[0],        v001 = p[1];
                const float v010 = p[OY],       v011 = p[OY + 1];
                const float v100 = p[OX],       v101 = p[OX + 1];
                const float v110 = p[OX + OY],  v111 = p[OX + OY + 1];

                const float c00 = fmaf(v001, wcz, v000 * wfz);
                const float c01 = fmaf(v011, wcz, v010 * wfz);
                const float c10 = fmaf(v101, wcz, v100 * wfz);
                const float c11 = fmaf(v111, wcz, v110 * wfz);
                const float c0  = fmaf(c01, wcy, c00 * wfy);
                const float c1  = fmaf(c11, wcy, c10 * wfy);
                outp[e << 16]   = fmaf(c1,  wcx, c0  * wfx);
            }
        } else {
            float fi = (float)i0;
#pragma unroll
            for (int e = 0; e < TI; e++) {
                const float II = fmaf(T00, fi, IIb);
                const float JJ = fmaf(T10, fi, JJb);
                const float KK = fmaf(T20, fi, KKb);
                fi += 1.0f;

                const float cmin = fminf(fminf(II, JJ), KK);
                const float cmax = fmaxf(fmaxf(II, JJ), KK);
                const bool ok = (cmin > 0.0f) & (cmax <= 255.0f);

                const float fx = floorf(II);
                const float fy = floorf(JJ);
                const float fz = floorf(KK);
                const float wcx = II - fx, wfx = 1.0f - wcx;
                const float wcy = JJ - fy, wfy = 1.0f - wcy;
                const float wcz = KK - fz, wfz = 1.0f - wcz;

                int base = __float2int_rn(
                    fmaf(fx, (float)OX, fmaf(fy, (float)OY, fz))) + Coff;
                base = min(max(base, 0), BASE_LIM);   // ok=false coords -> safe addr
                const float* p = tilep + base;

                const float v000 = p[0],        v001 = p[1];
                const float v010 = p[OY],       v011 = p[OY + 1];
                const float v100 = p[OX],       v101 = p[OX + 1];
                const float v110 = p[OX + OY],  v111 = p[OX + OY + 1];

                const float c00 = fmaf(v001, wcz, v000 * wfz);
                const float c01 = fmaf(v011, wcz, v010 * wfz);
                const float c10 = fmaf(v101, wcz, v100 * wfz);
                const float c11 = fmaf(v111, wcz, v110 * wfz);
                const float c0  = fmaf(c01, wcy, c00 * wfy);
                const float c1  = fmaf(c11, wcy, c10 * wfy);
                float v         = fmaf(c1,  wcx, c0  * wfx);

                outp[e << 16] = ok ? v : 0.0f;
            }
        }
    } else {
        // ---------------- fallback: direct global gather ----------------
        float fi = (float)i0;
        for (int e = 0; e < TI; e++) {
            const float II = fmaf(T00, fi, IIb);
            const float JJ = fmaf(T10, fi, JJb);
            const float KK = fmaf(T20, fi, KKb);
            fi += 1.0f;

            const bool ok = (II > 0.0f) & (JJ > 0.0f) & (KK > 0.0f) &
                            (II <= 255.0f) & (JJ <= 255.0f) & (KK <= 255.0f);
            float v = 0.0f;
            if (ok) {
                const int x0 = __float2int_rd(II);
                const int y0 = __float2int_rd(JJ);
                const int z0 = __float2int_rd(KK);
                const float wcx = II - (float)x0, wfx = 1.0f - wcx;
                const float wcy = JJ - (float)y0, wfy = 1.0f - wcy;
                const float wcz = KK - (float)z0, wfz = 1.0f - wcz;

                const int ox = (x0 < 255) ? 65536 : 0;
                const int oy = (y0 < 255) ? 256 : 0;
                const int oz = (z0 < 255) ? 1 : 0;

                const float* p = img + ((x0 << 16) | (y0 << 8) | z0);
                const float v000 = __ldg(p),            v001 = __ldg(p + oz);
                const float v010 = __ldg(p + oy),       v011 = __ldg(p + oy + oz);
                const float v100 = __ldg(p + ox),       v101 = __ldg(p + ox + oz);
                const float v110 = __ldg(p + ox + oy),  v111 = __ldg(p + ox + oy + oz);

                const float c00 = fmaf(v001, wcz, v000 * wfz);
                const float c01 = fmaf(v011, wcz, v010 * wfz);
                const float c10 = fmaf(v101, wcz, v100 * wfz);
                const float c11 = fmaf(v111, wcz, v110 * wfz);
                const float c0  = fmaf(c01, wcy, c00 * wfy);
                const float c1  = fmaf(c11, wcy, c10 * wfy);
                v               = fmaf(c1,  wcx, c0  * wfx);
            }
            outp[e << 16] = v;
        }
    }
}

// -------------------- cp.async fallback kernel (known-good) -----------------
__device__ __forceinline__ void cp_async16(unsigned int smem_dst, const void* gsrc) {
    asm volatile("cp.async.cg.shared.global [%0], [%1], 16;\n"
                 :: "r"(smem_dst), "l"(gsrc) : "memory");
}
__device__ __forceinline__ void cp_async_wait_all() {
    asm volatile("cp.async.commit_group;\ncp.async.wait_group 0;\n" ::: "memory");
}

__global__ void __launch_bounds__(NTHREADS, 3)
lds_trilinear_kernel(const float* __restrict__ img, float* __restrict__ out) {
    extern __shared__ __align__(128) float tile[];

    const int bid = blockIdx.x;
    const int k0 = (bid & 7) << 5;
    const int j0 = ((bid >> 3) & 15) << 4;
    const int i0 = (bid >> 7) << 3;

    const float T00 = g_T[0], T01 = g_T[1],  T02 = g_T[2],  T03 = g_T[3];
    const float T10 = g_T[4], T11 = g_T[5],  T12 = g_T[6],  T13 = g_T[7];
    const float T20 = g_T[8], T21 = g_T[9],  T22 = g_T[10], T23 = g_T[11];

    const float mnI = T03 + axis_min(T00, i0, TI) + axis_min(T01, j0, TJ) + axis_min(T02, k0, TK);
    const float mxI = T03 + axis_max(T00, i0, TI) + axis_max(T01, j0, TJ) + axis_max(T02, k0, TK);
    const float mnJ = T13 + axis_min(T10, i0, TI) + axis_min(T11, j0, TJ) + axis_min(T12, k0, TK);
    const float mxJ = T13 + axis_max(T10, i0, TI) + axis_max(T11, j0, TJ) + axis_max(T12, k0, TK);
    const float mnK = T23 + axis_min(T20, i0, TI) + axis_min(T21, j0, TJ) + axis_min(T22, k0, TK);
    const float mxK = T23 + axis_max(T20, i0, TI) + axis_max(T21, j0, TJ) + axis_max(T22, k0, TK);

    const int loX  = max(__float2int_rd(mnI), 0);
    const int loY  = max(__float2int_rd(mnJ), 0);
    const int loZ  = max(__float2int_rd(mnK), 0);
    const int zloA = loZ & ~3;
    const int hiX  = min(__float2int_rd(mxI) + 1, 255);
    const int hiY  = min(__float2int_rd(mxJ) + 1, 255);
    const int hiZ  = min(__float2int_rd(mxK) + 1, 255);

    const bool fits = (hiX - loX < SMX) && (hiY - loY < SMY) && (hiZ - zloA < 44);

    const int tid = threadIdx.x;
    const int kl = tid & 31;
    const int tg = tid >> 5;
    const int k = k0 + kl;
    const int j = j0 + tg;
    const float fk = (float)k, fj = (float)j;

    const float IIb = fmaf(T01, fj, fmaf(T02, fk, T03));
    const float JJb = fmaf(T11, fj, fmaf(T12, fk, T13));
    const float KKb = fmaf(T21, fj, fmaf(T22, fk, T23));

    float* outp = out + (((i0 << 8) | j) << 8 | k);

    if (fits) {
        {
            const unsigned int sm0 = smem_u32(&tile[0]);
            constexpr int NQ = 11;
            constexpr int NQUADS = SMX * SMY * NQ;
            for (int idx = tid; idx < NQUADS; idx += NTHREADS) {
                const int r  = idx / NQ;
                const int q  = idx - r * NQ;
                const int xp = r / SMY;
                const int yp = r - xp * SMY;
                const int xg = min(loX + xp, 255);
                const int yg = min(loY + yp, 255);
                const int zg = min(zloA + (q << 2), 252);
                cp_async16(sm0 + ((r << 6) + (q << 2)) * 4,
                           img + ((xg << 16) | (yg << 8) | zg));
            }
            cp_async_wait_all();
        }
        __syncthreads();

        const int Coff = -(loX * OX + loY * OY + zloA);
        const float* tilep = tile;

        float fi = (float)i0;
#pragma unroll
        for (int e = 0; e < TI; e++) {
            const float II = fmaf(T00, fi, IIb);
            const float JJ = fmaf(T10, fi, JJb);
            const float KK = fmaf(T20, fi, KKb);
            fi += 1.0f;

            const float cmin = fminf(fminf(II, JJ), KK);
            const float cmax = fmaxf(fmaxf(II, JJ), KK);
            const bool ok = (cmin > 0.0f) & (cmax <= 255.0f);

            const float fx = floorf(II);
            const float fy = floorf(JJ);
            const float fz = floorf(KK);
            const float wcx = II - fx, wfx = 1.0f - wcx;
            const float wcy = JJ - fy, wfy = 1.0f - wcy;
            const float wcz = KK - fz, wfz = 1.0f - wcz;

            int base = __float2int_rn(
                fmaf(fx, (float)OX, fmaf(fy, (float)OY, fz))) + Coff;
            base = min(max(base, 0), BASE_LIM);
            const float* p = tilep + base;

            const float v000 = p[0],        v001 = p[1];
            const float v010 = p[OY],       v011 = p[OY + 1];
            const float v100 = p[OX],       v101 = p[OX + 1];
            const float v110 = p[OX + OY],  v111 = p[OX + OY + 1];

            const float c00 = fmaf(v001, wcz, v000 * wfz);
            const float c01 = fmaf(v011, wcz, v010 * wfz);
            const float c10 = fmaf(v101, wcz, v100 * wfz);
            const float c11 = fmaf(v111, wcz, v110 * wfz);
            const float c0  = fmaf(c01, wcy, c00 * wfy);
            const float c1  = fmaf(c11, wcy, c10 * wfy);
            float v         = fmaf(c1,  wcx, c0  * wfx);

            outp[e << 16] = ok ? v : 0.0f;
        }
    } else {
        float fi = (float)i0;
        for (int e = 0; e < TI; e++) {
            const float II = fmaf(T00, fi, IIb);
            const float JJ = fmaf(T10, fi, JJb);
            const float KK = fmaf(T20, fi, KKb);
            fi += 1.0f;

            const bool ok = (II > 0.0f) & (JJ > 0.0f) & (KK > 0.0f) &
                            (II <= 255.0f) & (JJ <= 255.0f) & (KK <= 255.0f);
            float v = 0.0f;
            if (ok) {
                const int x0 = __float2int_rd(II);
                const int y0 = __float2int_rd(JJ);
                const int z0 = __float2int_rd(KK);
                const float wcx = II - (float)x0, wfx = 1.0f - wcx;
                const float wcy = JJ - (float)y0, wfy = 1.0f - wcy;
                const float wcz = KK - (float)z0, wfz = 1.0f - wcz;

                const int ox = (x0 < 255) ? 65536 : 0;
                const int oy = (y0 < 255) ? 256 : 0;
                const int oz = (z0 < 255) ? 1 : 0;

                const float* p = img + ((x0 << 16) | (y0 << 8) | z0);
                const float v000 = __ldg(p),            v001 = __ldg(p + oz);
                const float v010 = __ldg(p + oy),       v011 = __ldg(p + oy + oz);
                const float v100 = __ldg(p + ox),       v101 = __ldg(p + ox + oz);
                const float v110 = __ldg(p + ox + oy),  v111 = __ldg(p + ox + oy + oz);

                const float c00 = fmaf(v001, wcz, v000 * wfz);
                const float c01 = fmaf(v011, wcz, v010 * wfz);
                const float c10 = fmaf(v101, wcz, v100 * wfz);
                const float c11 = fmaf(v111, wcz, v110 * wfz);
                const float c0  = fmaf(c01, wcy, c00 * wfy);
                const float c1  = fmaf(c11, wcy, c10 * wfy);
                v               = fmaf(c1,  wcx, c0  * wfx);
            }
            outp[e << 16] = v;
        }
    }
}

// ------------------------------- host side ----------------------------------
typedef CUresult (*EncodeTiledFn)(
    CUtensorMap*, CUtensorMapDataType, cuuint32_t, void*,
    const cuuint64_t*, const cuuint64_t*, const cuuint32_t*, const cuuint32_t*,
    CUtensorMapInterleave, CUtensorMapSwizzle, CUtensorMapL2promotion,
    CUtensorMapFloatOOBfill);

extern "C" void kernel_launch(void* const* d_in, const int* in_sizes, int n_in,
                              void* d_out, int out_size) {
    const float* img         = (const float*)d_in[0];
    const float* rotation    = (const float*)d_in[1];
    const float* translation = (const float*)d_in[2];
    const float* ref_v2r     = (const float*)d_in[3];
    const float* flo_v2r     = (const float*)d_in[4];
    float* out = (float*)d_out;

    setup_transform_kernel<<<1, 1>>>(rotation, translation, ref_v2r, flo_v2r);

    static bool attr_set = false;
    if (!attr_set) {
        cudaFuncSetAttribute(tma_trilinear_kernel,
                             cudaFuncAttributeMaxDynamicSharedMemorySize, SM_BYTES);
        cudaFuncSetAttribute(lds_trilinear_kernel,
                             cudaFuncAttributeMaxDynamicSharedMemorySize, SM_BYTES);
        attr_set = true;
    }

    // Resolve cuTensorMapEncodeTiled through the runtime (no -lcuda needed).
    static EncodeTiledFn encode_fn = nullptr;
    static bool resolved = false;
    if (!resolved) {
        void* fp = nullptr;
        cudaDriverEntryPointQueryResult qres;
#if CUDART_VERSION >= 12050
        if (cudaGetDriverEntryPointByVersion("cuTensorMapEncodeTiled", &fp, 12000,
                                             cudaEnableDefault, &qres) == cudaSuccess &&
            qres == cudaDriverEntryPointSuccess)
            encode_fn = (EncodeTiledFn)fp;
#else
        if (cudaGetDriverEntryPoint("cuTensorMapEncodeTiled", &fp,
                                    cudaEnableDefault, &qres) == cudaSuccess &&
            qres == cudaDriverEntryPointSuccess)
            encode_fn = (EncodeTiledFn)fp;
#endif
        resolved = true;
    }

    bool tma_ok = false;
    CUtensorMap tmap;
    if (encode_fn) {
        cuuint64_t dims[3]    = {256, 256, 256};
        cuuint64_t strides[2] = {256 * 4, 256 * 256 * 4};
        cuuint32_t box[3]     = {(cuuint32_t)OY, (cuuint32_t)SMY, (cuuint32_t)SMX};
        cuuint32_t estr[3]    = {1, 1, 1};
        CUresult r = encode_fn(&tmap, CU_TENSOR_MAP_DATA_TYPE_FLOAT32, 3,
                               (void*)img, dims, strides, box, estr,
                               CU_TENSOR_MAP_INTERLEAVE_NONE,
                               CU_TENSOR_MAP_SWIZZLE_NONE,
                               CU_TENSOR_MAP_L2_PROMOTION_L2_128B,
                               CU_TENSOR_MAP_FLOAT_OOB_FILL_NONE);
        tma_ok = (r == CUDA_SUCCESS);
    }

    if (tma_ok) {
        tma_trilinear_kernel<<<4096, NTHREADS, SM_BYTES>>>(tmap, img, out);
    } else {
        lds_trilinear_kernel<<<4096, NTHREADS, SM_BYTES>>>(img, out);
    }
}

// round 14
// speedup vs baseline: 1.3610x; 1.0663x over previous
#include <cuda_runtime.h>
#include <cuda.h>
#include <cstdint>

// ---------------------------------------------------------------------------
// InstanceModelClassic: rigid-transform trilinear resampling of a 256^3 volume
// TMA-staged smem tile (conflict-free 64-float pitch), interior fast path,
// per-block tile metadata precomputed in the setup launch.
// ---------------------------------------------------------------------------

__device__ float g_T[12];       // 3x4 rows of composed voxel->voxel transform
__device__ int4  g_meta[4096];  // per-block {loX, loY, zloA, flags}

// ----------------------------------------------------------------------------
// Tile geometry.
//   Output tile: TI x TJ x TK = 8 x 16 x 32  (4096 voxels, 4096 blocks)
//   Staged via TMA box (z,y,x) = (64, 21, 14) fp32, OOB zero-filled.
//   OY = 64 floats (256B == 0 mod 32 banks), OX = 64*21 = 1344 (== 0 mod 32)
//   -> zero bank conflicts on all 8 gather taps.
//   smem = 75264 B tile + mbarrier -> 3 CTA/SM, 48 warps/SM.
// ----------------------------------------------------------------------------
constexpr int TI = 8, TJ = 16, TK = 32;
constexpr int SMX = 14, SMY = 21;
constexpr int OY = 64;                    // z pitch (floats)
constexpr int OX = OY * SMY;              // 1344
constexpr int SM_FLOATS = SMX * SMY * OY; // 18816
constexpr int TILE_BYTES = SM_FLOATS * 4; // 75264
constexpr int SM_BYTES = TILE_BYTES + 16; // + mbarrier slot
constexpr int NTHREADS = 512;
constexpr int BASE_LIM = SM_FLOATS - (OX + OY + 2);  // 17406

__device__ static void mat4_inv(const float* A, float* Ainv) {
    float M[4][8];
    for (int r = 0; r < 4; r++) {
        for (int c = 0; c < 4; c++) {
            M[r][c] = A[r * 4 + c];
            M[r][4 + c] = (r == c) ? 1.0f : 0.0f;
        }
    }
    for (int col = 0; col < 4; col++) {
        int piv = col;
        float best = fabsf(M[col][col]);
        for (int r = col + 1; r < 4; r++) {
            float v = fabsf(M[r][col]);
            if (v > best) { best = v; piv = r; }
        }
        if (piv != col)
            for (int c = 0; c < 8; c++) {
                float t = M[col][c]; M[col][c] = M[piv][c]; M[piv][c] = t;
            }
        float inv_p = 1.0f / M[col][col];
        for (int c = 0; c < 8; c++) M[col][c] *= inv_p;
        for (int r = 0; r < 4; r++) {
            if (r == col) continue;
            float f = M[r][col];
            if (f != 0.0f)
                for (int c = 0; c < 8; c++) M[r][c] -= f * M[col][c];
        }
    }
    for (int r = 0; r < 4; r++)
        for (int c = 0; c < 4; c++)
            Ainv[r * 4 + c] = M[r][4 + c];
}

__device__ static void mm4(const float* A, const float* B, float* C) {
    for (int r = 0; r < 4; r++)
        for (int c = 0; c < 4; c++) {
            float s = 0.0f;
            for (int k = 0; k < 4; k++) s += A[r * 4 + k] * B[k * 4 + c];
            C[r * 4 + c] = s;
        }
}

__device__ static void compute_T(const float* rotation, const float* translation,
                                 const float* ref_v2r, const float* flo_v2r,
                                 float* Tout /*12*/) {
    float cx = cosf(rotation[0]), cy = cosf(rotation[1]), cz = cosf(rotation[2]);
    float sx = sinf(rotation[0]), sy = sinf(rotation[1]), sz = sinf(rotation[2]);

    float Rx[9] = {1, 0, 0,   0, cx, -sx,   0, sx, cx};
    float Ry[9] = {cy, 0, sy, 0, 1, 0,      -sy, 0, cy};
    float Rz[9] = {cz, -sz, 0, sz, cz, 0,   0, 0, 1};
    float Ryz[9], R[9];
    for (int r = 0; r < 3; r++)
        for (int c = 0; c < 3; c++) {
            float s = 0.0f;
            for (int k = 0; k < 3; k++) s += Ry[r * 3 + k] * Rz[k * 3 + c];
            Ryz[r * 3 + c] = s;
        }
    for (int r = 0; r < 3; r++)
        for (int c = 0; c < 3; c++) {
            float s = 0.0f;
            for (int k = 0; k < 3; k++) s += Rx[r * 3 + k] * Ryz[k * 3 + c];
            R[r * 3 + c] = s;
        }

    float Trig[16];
    for (int r = 0; r < 3; r++) {
        for (int c = 0; c < 3; c++) Trig[r * 4 + c] = R[r * 3 + c];
        Trig[r * 4 + 3] = translation[r];
    }
    Trig[12] = 0.0f; Trig[13] = 0.0f; Trig[14] = 0.0f; Trig[15] = 1.0f;

    float Finv[16], tmp[16], T[16];
    mat4_inv(flo_v2r, Finv);
    mm4(Trig, ref_v2r, tmp);
    mm4(Finv, tmp, T);

    for (int i = 0; i < 12; i++) Tout[i] = T[i];
}

__device__ __forceinline__ float axis_min(float t, int lo, int len) {
    return (t >= 0.0f) ? t * (float)lo : t * (float)(lo + len - 1);
}
__device__ __forceinline__ float axis_max(float t, int lo, int len) {
    return (t >= 0.0f) ? t * (float)(lo + len - 1) : t * (float)lo;
}

// Setup launch: every thread computes T (redundant, cheap), thread 0 publishes
// g_T, each thread computes its block's tile metadata.
__global__ void meta_kernel(const float* __restrict__ rotation,
                            const float* __restrict__ translation,
                            const float* __restrict__ ref_v2r,
                            const float* __restrict__ flo_v2r) {
    float T[12];
    compute_T(rotation, translation, ref_v2r, flo_v2r, T);

    const int t = blockIdx.x * blockDim.x + threadIdx.x;   // 0..4095
    if (t == 0)
        for (int i = 0; i < 12; i++) g_T[i] = T[i];

    const int k0 = (t & 7) << 5;
    const int j0 = ((t >> 3) & 15) << 4;
    const int i0 = (t >> 7) << 3;

    const float mnI = T[3]  + axis_min(T[0], i0, TI) + axis_min(T[1], j0, TJ) + axis_min(T[2], k0, TK);
    const float mxI = T[3]  + axis_max(T[0], i0, TI) + axis_max(T[1], j0, TJ) + axis_max(T[2], k0, TK);
    const float mnJ = T[7]  + axis_min(T[4], i0, TI) + axis_min(T[5], j0, TJ) + axis_min(T[6], k0, TK);
    const float mxJ = T[7]  + axis_max(T[4], i0, TI) + axis_max(T[5], j0, TJ) + axis_max(T[6], k0, TK);
    const float mnK = T[11] + axis_min(T[8], i0, TI) + axis_min(T[9], j0, TJ) + axis_min(T[10], k0, TK);
    const float mxK = T[11] + axis_max(T[8], i0, TI) + axis_max(T[9], j0, TJ) + axis_max(T[10], k0, TK);

    const int loX  = max(__float2int_rd(mnI), 0);
    const int loY  = max(__float2int_rd(mnJ), 0);
    const int loZ  = max(__float2int_rd(mnK), 0);
    const int zloA = loZ & ~3;
    const int hiX  = min(__float2int_rd(mxI) + 1, 255);
    const int hiY  = min(__float2int_rd(mxJ) + 1, 255);
    const int hiZ  = min(__float2int_rd(mxK) + 1, 255);

    const bool fits = (hiX - loX < SMX) && (hiY - loY < SMY) && (hiZ - zloA < OY);
    const bool interior = (mnI > 0.01f) && (mxI < 254.99f) &&
                          (mnJ > 0.01f) && (mxJ < 254.99f) &&
                          (mnK > 0.01f) && (mxK < 254.99f);

    g_meta[t] = make_int4(loX, loY, zloA, (fits ? 1 : 0) | (interior ? 2 : 0));
}

__device__ __forceinline__ unsigned int smem_u32(const void* p) {
    return (unsigned int)__cvta_generic_to_shared(p);
}
__device__ __forceinline__ void mbar_init(unsigned int mbar, unsigned int cnt) {
    asm volatile("mbarrier.init.shared.b64 [%0], %1;" :: "r"(mbar), "r"(cnt) : "memory");
}
__device__ __forceinline__ void mbar_expect_tx(unsigned int mbar, unsigned int bytes) {
    asm volatile("mbarrier.arrive.expect_tx.shared.b64 _, [%0], %1;"
                 :: "r"(mbar), "r"(bytes) : "memory");
}
__device__ __forceinline__ void mbar_wait_parity0(unsigned int mbar) {
    asm volatile(
        "{\n\t"
        ".reg .pred P1;\n\t"
        "WAIT_LOOP_%=:\n\t"
        "mbarrier.try_wait.parity.acquire.cta.shared::cta.b64 P1, [%0], 0, 0x989680;\n\t"
        "@P1 bra.uni WAIT_DONE_%=;\n\t"
        "bra.uni WAIT_LOOP_%=;\n\t"
        "WAIT_DONE_%=:\n\t"
        "}"
        :: "r"(mbar) : "memory");
}
__device__ __forceinline__ void tma_load_3d(unsigned int dst, const CUtensorMap* tmap,
                                            int c0, int c1, int c2, unsigned int mbar) {
    asm volatile(
        "cp.async.bulk.tensor.3d.shared::cta.global.tile.mbarrier::complete_tx::bytes "
        "[%0], [%1, {%2, %3, %4}], [%5];"
        :: "r"(dst), "l"(tmap), "r"(c0), "r"(c1), "r"(c2), "r"(mbar) : "memory");
}

// ---------------------------- TMA-staged kernel -----------------------------
__global__ void __launch_bounds__(NTHREADS, 3)
tma_trilinear_kernel(const __grid_constant__ CUtensorMap tmap,
                     const float* __restrict__ img, float* __restrict__ out) {
    extern __shared__ __align__(128) float tile[];

    const int bid = blockIdx.x;
    const int k0 = (bid & 7) << 5;
    const int j0 = ((bid >> 3) & 15) << 4;
    const int i0 = (bid >> 7) << 3;

    const int4 meta = g_meta[bid];
    const bool fits     = (meta.w & 1) != 0;
    const bool interior = (meta.w & 2) != 0;

    const float T00 = g_T[0], T01 = g_T[1],  T02 = g_T[2],  T03 = g_T[3];
    const float T10 = g_T[4], T11 = g_T[5],  T12 = g_T[6],  T13 = g_T[7];
    const float T20 = g_T[8], T21 = g_T[9],  T22 = g_T[10], T23 = g_T[11];

    const int tid = threadIdx.x;
    const int kl = tid & 31;        // k lane (warp-contiguous)
    const int tg = tid >> 5;        // j row within tile
    const int k = k0 + kl;
    const int j = j0 + tg;
    const float fk = (float)k, fj = (float)j;

    const float IIb = fmaf(T01, fj, fmaf(T02, fk, T03));
    const float JJb = fmaf(T11, fj, fmaf(T12, fk, T13));
    const float KKb = fmaf(T21, fj, fmaf(T22, fk, T23));

    float* outp = out + (((i0 << 8) | j) << 8 | k);

    if (fits) {
        // ---- one TMA bulk load stages the whole tile; OOB zero-filled ----
        const unsigned int mbar = smem_u32(&tile[SM_FLOATS]);
        if (tid == 0) {
            mbar_init(mbar, 1);
        }
        __syncthreads();
        if (tid == 0) {
            mbar_expect_tx(mbar, TILE_BYTES);
            tma_load_3d(smem_u32(&tile[0]), &tmap, meta.z, meta.y, meta.x, mbar);
        }
        mbar_wait_parity0(mbar);

        const int Coff = -(meta.x * OX + meta.y * OY + meta.z);
        const float* tilep = tile;

        if (interior) {
            float fi = (float)i0;
#pragma unroll
            for (int e = 0; e < TI; e++) {
                const float II = fmaf(T00, fi, IIb);
                const float JJ = fmaf(T10, fi, JJb);
                const float KK = fmaf(T20, fi, KKb);
                fi += 1.0f;

                const float fx = floorf(II);
                const float fy = floorf(JJ);
                const float fz = floorf(KK);
                const float wcx = II - fx, wfx = 1.0f - wcx;
                const float wcy = JJ - fy, wfy = 1.0f - wcy;
                const float wcz = KK - fz, wfz = 1.0f - wcz;

                const int base = __float2int_rn(
                    fmaf(fx, (float)OX, fmaf(fy, (float)OY, fz))) + Coff;
                const float* p = tilep + base;

                const float v000 = p[0],        v001 = p[1];
                const float v010 = p[OY],       v011 = p[OY + 1];
                const float v100 = p[OX],       v101 = p[OX + 1];
                const float v110 = p[OX + OY],  v111 = p[OX + OY + 1];

                const float c00 = fmaf(v001, wcz, v000 * wfz);
                const float c01 = fmaf(v011, wcz, v010 * wfz);
                const float c10 = fmaf(v101, wcz, v100 * wfz);
                const float c11 = fmaf(v111, wcz, v110 * wfz);
                const float c0  = fmaf(c01, wcy, c00 * wfy);
                const float c1  = fmaf(c11, wcy, c10 * wfy);
                outp[e << 16]   = fmaf(c1,  wcx, c0  * wfx);
            }
        } else {
            float fi = (float)i0;
#pragma unroll
            for (int e = 0; e < TI; e++) {
                const float II = fmaf(T00, fi, IIb);
                const float JJ = fmaf(T10, fi, JJb);
                const float KK = fmaf(T20, fi, KKb);
                fi += 1.0f;

                const float cmin = fminf(fminf(II, JJ), KK);
                const float cmax = fmaxf(fmaxf(II, JJ), KK);
                const bool ok = (cmin > 0.0f) & (cmax <= 255.0f);

                const float fx = floorf(II);
                const float fy = floorf(JJ);
                const float fz = floorf(KK);
                const float wcx = II - fx, wfx = 1.0f - wcx;
                const float wcy = JJ - fy, wfy = 1.0f - wcy;
                const float wcz = KK - fz, wfz = 1.0f - wcz;

                int base = __float2int_rn(
                    fmaf(fx, (float)OX, fmaf(fy, (float)OY, fz))) + Coff;
                base = min(max(base, 0), BASE_LIM);   // ok=false coords -> safe addr
                const float* p = tilep + base;

                const float v000 = p[0],        v001 = p[1];
                const float v010 = p[OY],       v011 = p[OY + 1];
                const float v100 = p[OX],       v101 = p[OX + 1];
                const float v110 = p[OX + OY],  v111 = p[OX + OY + 1];

                const float c00 = fmaf(v001, wcz, v000 * wfz);
                const float c01 = fmaf(v011, wcz, v010 * wfz);
                const float c10 = fmaf(v101, wcz, v100 * wfz);
                const float c11 = fmaf(v111, wcz, v110 * wfz);
                const float c0  = fmaf(c01, wcy, c00 * wfy);
                const float c1  = fmaf(c11, wcy, c10 * wfy);
                float v         = fmaf(c1,  wcx, c0  * wfx);

                outp[e << 16] = ok ? v : 0.0f;
            }
        }
    } else {
        // ---------------- fallback: direct global gather ----------------
        float fi = (float)i0;
        for (int e = 0; e < TI; e++) {
            const float II = fmaf(T00, fi, IIb);
            const float JJ = fmaf(T10, fi, JJb);
            const float KK = fmaf(T20, fi, KKb);
            fi += 1.0f;

            const bool ok = (II > 0.0f) & (JJ > 0.0f) & (KK > 0.0f) &
                            (II <= 255.0f) & (JJ <= 255.0f) & (KK <= 255.0f);
            float v = 0.0f;
            if (ok) {
                const int x0 = __float2int_rd(II);
                const int y0 = __float2int_rd(JJ);
                const int z0 = __float2int_rd(KK);
                const float wcx = II - (float)x0, wfx = 1.0f - wcx;
                const float wcy = JJ - (float)y0, wfy = 1.0f - wcy;
                const float wcz = KK - (float)z0, wfz = 1.0f - wcz;

                const int ox = (x0 < 255) ? 65536 : 0;
                const int oy = (y0 < 255) ? 256 : 0;
                const int oz = (z0 < 255) ? 1 : 0;

                const float* p = img + ((x0 << 16) | (y0 << 8) | z0);
                const float v000 = __ldg(p),            v001 = __ldg(p + oz);
                const float v010 = __ldg(p + oy),       v011 = __ldg(p + oy + oz);
                const float v100 = __ldg(p + ox),       v101 = __ldg(p + ox + oz);
                const float v110 = __ldg(p + ox + oy),  v111 = __ldg(p + ox + oy + oz);

                const float c00 = fmaf(v001, wcz, v000 * wfz);
                const float c01 = fmaf(v011, wcz, v010 * wfz);
                const float c10 = fmaf(v101, wcz, v100 * wfz);
                const float c11 = fmaf(v111, wcz, v110 * wfz);
                const float c0  = fmaf(c01, wcy, c00 * wfy);
                const float c1  = fmaf(c11, wcy, c10 * wfy);
                v               = fmaf(c1,  wcx, c0  * wfx);
            }
            outp[e << 16] = v;
        }
    }
}

// -------------------- cp.async fallback kernel (known-good) -----------------
__device__ __forceinline__ void cp_async16(unsigned int smem_dst, const void* gsrc) {
    asm volatile("cp.async.cg.shared.global [%0], [%1], 16;\n"
                 :: "r"(smem_dst), "l"(gsrc) : "memory");
}
__device__ __forceinline__ void cp_async_wait_all() {
    asm volatile("cp.async.commit_group;\ncp.async.wait_group 0;\n" ::: "memory");
}

__global__ void __launch_bounds__(NTHREADS, 3)
lds_trilinear_kernel(const float* __restrict__ img, float* __restrict__ out) {
    extern __shared__ __align__(128) float tile[];

    const int bid = blockIdx.x;
    const int k0 = (bid & 7) << 5;
    const int j0 = ((bid >> 3) & 15) << 4;
    const int i0 = (bid >> 7) << 3;

    const int4 meta = g_meta[bid];
    const bool fits = (meta.w & 1) != 0;

    const float T00 = g_T[0], T01 = g_T[1],  T02 = g_T[2],  T03 = g_T[3];
    const float T10 = g_T[4], T11 = g_T[5],  T12 = g_T[6],  T13 = g_T[7];
    const float T20 = g_T[8], T21 = g_T[9],  T22 = g_T[10], T23 = g_T[11];

    const int tid = threadIdx.x;
    const int kl = tid & 31;
    const int tg = tid >> 5;
    const int k = k0 + kl;
    const int j = j0 + tg;
    const float fk = (float)k, fj = (float)j;

    const float IIb = fmaf(T01, fj, fmaf(T02, fk, T03));
    const float JJb = fmaf(T11, fj, fmaf(T12, fk, T13));
    const float KKb = fmaf(T21, fj, fmaf(T22, fk, T23));

    float* outp = out + (((i0 << 8) | j) << 8 | k);

    if (fits) {
        {
            const unsigned int sm0 = smem_u32(&tile[0]);
            constexpr int NQ = 11;
            constexpr int NQUADS = SMX * SMY * NQ;
            for (int idx = tid; idx < NQUADS; idx += NTHREADS) {
                const int r  = idx / NQ;
                const int q  = idx - r * NQ;
                const int xp = r / SMY;
                const int yp = r - xp * SMY;
                const int xg = min(meta.x + xp, 255);
                const int yg = min(meta.y + yp, 255);
                const int zg = min(meta.z + (q << 2), 252);
                cp_async16(sm0 + ((r << 6) + (q << 2)) * 4,
                           img + ((xg << 16) | (yg << 8) | zg));
            }
            cp_async_wait_all();
        }
        __syncthreads();

        const int Coff = -(meta.x * OX + meta.y * OY + meta.z);
        const float* tilep = tile;

        float fi = (float)i0;
#pragma unroll
        for (int e = 0; e < TI; e++) {
            const float II = fmaf(T00, fi, IIb);
            const float JJ = fmaf(T10, fi, JJb);
            const float KK = fmaf(T20, fi, KKb);
            fi += 1.0f;

            const float cmin = fminf(fminf(II, JJ), KK);
            const float cmax = fmaxf(fmaxf(II, JJ), KK);
            const bool ok = (cmin > 0.0f) & (cmax <= 255.0f);

            const float fx = floorf(II);
            const float fy = floorf(JJ);
            const float fz = floorf(KK);
            const float wcx = II - fx, wfx = 1.0f - wcx;
            const float wcy = JJ - fy, wfy = 1.0f - wcy;
            const float wcz = KK - fz, wfz = 1.0f - wcz;

            int base = __float2int_rn(
                fmaf(fx, (float)OX, fmaf(fy, (float)OY, fz))) + Coff;
            base = min(max(base, 0), BASE_LIM);
            const float* p = tilep + base;

            const float v000 = p[0],        v001 = p[1];
            const float v010 = p[OY],       v011 = p[OY + 1];
            const float v100 = p[OX],       v101 = p[OX + 1];
            const float v110 = p[OX + OY],  v111 = p[OX + OY + 1];

            const float c00 = fmaf(v001, wcz, v000 * wfz);
            const float c01 = fmaf(v011, wcz, v010 * wfz);
            const float c10 = fmaf(v101, wcz, v100 * wfz);
            const float c11 = fmaf(v111, wcz, v110 * wfz);
            const float c0  = fmaf(c01, wcy, c00 * wfy);
            const float c1  = fmaf(c11, wcy, c10 * wfy);
            float v         = fmaf(c1,  wcx, c0  * wfx);

            outp[e << 16] = ok ? v : 0.0f;
        }
    } else {
        float fi = (float)i0;
        for (int e = 0; e < TI; e++) {
            const float II = fmaf(T00, fi, IIb);
            const float JJ = fmaf(T10, fi, JJb);
            const float KK = fmaf(T20, fi, KKb);
            fi += 1.0f;

            const bool ok = (II > 0.0f) & (JJ > 0.0f) & (KK > 0.0f) &
                            (II <= 255.0f) & (JJ <= 255.0f) & (KK <= 255.0f);
            float v = 0.0f;
            if (ok) {
                const int x0 = __float2int_rd(II);
                const int y0 = __float2int_rd(JJ);
                const int z0 = __float2int_rd(KK);
                const float wcx = II - (float)x0, wfx = 1.0f - wcx;
                const float wcy = JJ - (float)y0, wfy = 1.0f - wcy;
                const float wcz = KK - (float)z0, wfz = 1.0f - wcz;

                const int ox = (x0 < 255) ? 65536 : 0;
                const int oy = (y0 < 255) ? 256 : 0;
                const int oz = (z0 < 255) ? 1 : 0;

                const float* p = img + ((x0 << 16) | (y0 << 8) | z0);
                const float v000 = __ldg(p),            v001 = __ldg(p + oz);
                const float v010 = __ldg(p + oy),       v011 = __ldg(p + oy + oz);
                const float v100 = __ldg(p + ox),       v101 = __ldg(p + ox + oz);
                const float v110 = __ldg(p + ox + oy),  v111 = __ldg(p + ox + oy + oz);

                const float c00 = fmaf(v001, wcz, v000 * wfz);
                const float c01 = fmaf(v011, wcz, v010 * wfz);
                const float c10 = fmaf(v101, wcz, v100 * wfz);
                const float c11 = fmaf(v111, wcz, v110 * wfz);
                const float c0  = fmaf(c01, wcy, c00 * wfy);
                const float c1  = fmaf(c11, wcy, c10 * wfy);
                v               = fmaf(c1,  wcx, c0  * wfx);
            }
            outp[e << 16] = v;
        }
    }
}

// ------------------------------- host side ----------------------------------
typedef CUresult (*EncodeTiledFn)(
    CUtensorMap*, CUtensorMapDataType, cuuint32_t, void*,
    const cuuint64_t*, const cuuint64_t*, const cuuint32_t*, const cuuint32_t*,
    CUtensorMapInterleave, CUtensorMapSwizzle, CUtensorMapL2promotion,
    CUtensorMapFloatOOBfill);

extern "C" void kernel_launch(void* const* d_in, const int* in_sizes, int n_in,
                              void* d_out, int out_size) {
    const float* img         = (const float*)d_in[0];
    const float* rotation    = (const float*)d_in[1];
    const float* translation = (const float*)d_in[2];
    const float* ref_v2r     = (const float*)d_in[3];
    const float* flo_v2r     = (const float*)d_in[4];
    float* out = (float*)d_out;

    meta_kernel<<<16, 256>>>(rotation, translation, ref_v2r, flo_v2r);

    static bool attr_set = false;
    if (!attr_set) {
        cudaFuncSetAttribute(tma_trilinear_kernel,
                             cudaFuncAttributeMaxDynamicSharedMemorySize, SM_BYTES);
        cudaFuncSetAttribute(lds_trilinear_kernel,
                             cudaFuncAttributeMaxDynamicSharedMemorySize, SM_BYTES);
        attr_set = true;
    }

    // Resolve cuTensorMapEncodeTiled through the runtime (no -lcuda needed).
    static EncodeTiledFn encode_fn = nullptr;
    static bool resolved = false;
    if (!resolved) {
        void* fp = nullptr;
        cudaDriverEntryPointQueryResult qres;
#if CUDART_VERSION >= 12050
        if (cudaGetDriverEntryPointByVersion("cuTensorMapEncodeTiled", &fp, 12000,
                                             cudaEnableDefault, &qres) == cudaSuccess &&
            qres == cudaDriverEntryPointSuccess)
            encode_fn = (EncodeTiledFn)fp;
#else
        if (cudaGetDriverEntryPoint("cuTensorMapEncodeTiled", &fp,
                                    cudaEnableDefault, &qres) == cudaSuccess &&
            qres == cudaDriverEntryPointSuccess)
            encode_fn = (EncodeTiledFn)fp;
#endif
        resolved = true;
    }

    bool tma_ok = false;
    CUtensorMap tmap;
    if (encode_fn) {
        cuuint64_t dims[3]    = {256, 256, 256};
        cuuint64_t strides[2] = {256 * 4, 256 * 256 * 4};
        cuuint32_t box[3]     = {(cuuint32_t)OY, (cuuint32_t)SMY, (cuuint32_t)SMX};
        cuuint32_t estr[3]    = {1, 1, 1};
        CUresult r = encode_fn(&tmap, CU_TENSOR_MAP_DATA_TYPE_FLOAT32, 3,
                               (void*)img, dims, strides, box, estr,
                               CU_TENSOR_MAP_INTERLEAVE_NONE,
                               CU_TENSOR_MAP_SWIZZLE_NONE,
                               CU_TENSOR_MAP_L2_PROMOTION_L2_128B,
                               CU_TENSOR_MAP_FLOAT_OOB_FILL_NONE);
        tma_ok = (r == CUDA_SUCCESS);
    }

    if (tma_ok) {
        tma_trilinear_kernel<<<4096, NTHREADS, SM_BYTES>>>(tmap, img, out);
    } else {
        lds_trilinear_kernel<<<4096, NTHREADS, SM_BYTES>>>(img, out);
    }
}